// round 8
// baseline (speedup 1.0000x reference)
#include <cuda_runtime.h>
#include <stdint.h>

// CTC batch loss, prob-domain forward with lazy biased power-of-2 rescaling.
// 2 INDEPENDENT warps per CTA (grid=128, block=64): warp w owns batch element
// b = 2*blockIdx + w with its own smem ring and its own recurrence; no per-step
// cross-warp coupling. This puts every warp on its own SMSP (wid 0 -> SMSP0,
// wid 1 -> SMSP1) with <=1 CTA per SM, eliminating the SMSP issue-port
// contention that bound rounds 4-7.
// Lane ln owns states [8*ln, 8*ln+8) (lane 31 also owns state 256). Alphas as
// f32x2 pairs; rows staged via cp.async in 4-row commit groups (32-row ring,
// 8 groups in flight); gathers double-buffered one block ahead.

namespace {
constexpr int kB = 256, kT = 512, kC = 256, kL = 128;
constexpr int kBlank = kC - 1;          // 255
constexpr float kEps = 1e-7f;
constexpr int kDepth = 32;              // smem ring rows per warp (power of 2)
constexpr int kGroup = 4;               // rows per commit group = steps per block
constexpr int kNG    = kT / kGroup;     // 128 groups
constexpr int kSmemBytes = 2 * kDepth * kC * 4;   // 64 KB dynamic

using ull = unsigned long long;

__device__ __forceinline__ void cp_async16(uint32_t saddr, const float* g) {
    asm volatile("cp.async.cg.shared.global [%0], [%1], 16;" :: "r"(saddr), "l"(g));
}
__device__ __forceinline__ void cp_commit() {
    asm volatile("cp.async.commit_group;" ::: "memory");
}
template <int N>
__device__ __forceinline__ void cp_wait() {
    asm volatile("cp.async.wait_group %0;" :: "n"(N) : "memory");
}
__device__ __forceinline__ uint32_t redux_max_u32(uint32_t v) {
    uint32_t r;
    asm volatile("redux.sync.max.u32 %0, %1, 0xffffffff;" : "=r"(r) : "r"(v));
    return r;
}
// f32x2 packed helpers (bit-level pack/unpack are register moves)
__device__ __forceinline__ ull pk2(float lo, float hi) {
    ull r;
    asm("mov.b64 %0, {%1, %2};" : "=l"(r) : "r"(__float_as_uint(lo)), "r"(__float_as_uint(hi)));
    return r;
}
__device__ __forceinline__ void unpk2(ull v, float& lo, float& hi) {
    uint32_t l, h;
    asm("mov.b64 {%0, %1}, %2;" : "=r"(l), "=r"(h) : "l"(v));
    lo = __uint_as_float(l); hi = __uint_as_float(h);
}
__device__ __forceinline__ ull add2(ull a, ull b) {
    ull r; asm("add.rn.f32x2 %0, %1, %2;" : "=l"(r) : "l"(a), "l"(b)); return r;
}
__device__ __forceinline__ ull mul2(ull a, ull b) {
    ull r; asm("mul.rn.f32x2 %0, %1, %2;" : "=l"(r) : "l"(a), "l"(b)); return r;
}
__device__ __forceinline__ ull fma2(ull a, ull b, ull c) {
    ull r; asm("fma.rn.f32x2 %0, %1, %2, %3;" : "=l"(r) : "l"(a), "l"(b), "l"(c)); return r;
}

struct RowP { ull pbb, q13, q57; float pb; };
} // namespace

__global__ void __launch_bounds__(64) ctc_loss_kernel(
    const int* __restrict__ y_true,     // [B, L] int32, values in [0, C-2]
    const float* __restrict__ y_pred,   // [B, T, C] float32 probabilities
    float* __restrict__ out)            // [B] float32 loss
{
    extern __shared__ __align__(16) float smem[];      // 2 rings, 32 KB each

    const int w  = threadIdx.x >> 5;                   // warp -> its own batch element
    const int ln = threadIdx.x & 31;
    const int b  = blockIdx.x * 2 + w;
    float* ring = smem + w * (kDepth * kC);

    // --- labels owned by this lane: indices 4*ln .. 4*ln+3 ---
    const int4 lab4 = reinterpret_cast<const int4*>(y_true + (size_t)b * kL)[ln];
    const int lab0 = lab4.x, lab1 = lab4.y, lab2 = lab4.z, lab3 = lab4.w;
    const int labm1 = __shfl_up_sync(0xffffffffu, lab3, 1);

    // skip for odd state s=2m+1: allowed iff s>=2 and label[m] != label[m-1]
    const float sk0f = (ln > 0 && lab0 != labm1) ? 1.f : 0.f;
    const ull sk01 = pk2(sk0f, (lab1 != lab0) ? 1.f : 0.f);
    const ull sk23 = pk2((lab2 != lab1) ? 1.f : 0.f, (lab3 != lab2) ? 1.f : 0.f);
    const ull eps2 = pk2(kEps, kEps);

    // --- cp.async staging: lane ln copies bytes [32*ln, 32*ln+32) of each 1KB row ---
    const float*   gbase = y_pred + (size_t)b * kT * kC + ln * 8;
    const uint32_t sbase = (uint32_t)__cvta_generic_to_shared(ring) + (uint32_t)ln * 32u;

    auto issue_group = [&](int g) {     // 4 rows per commit group (per-warp groups)
        if (g < kNG) {
#pragma unroll
            for (int j = 0; j < kGroup; j++) {
                int r = g * kGroup + j;
                uint32_t sa = sbase + (uint32_t)(r & (kDepth - 1)) * (kC * 4);
                const float* ga = gbase + (size_t)r * kC;
                cp_async16(sa, ga);
                cp_async16(sa + 16, ga + 4);
            }
        }
        cp_commit();                    // always commit: wait_group count invariant
    };

    // alphas: e01=(a0,a2) e23=(a4,a6) o01=(a1,a3) o23=(a5,a7); a8 = state 256
    ull e01 = 0, e23 = 0, o01 = 0, o23 = 0;
    float a8 = 0.f;
    int   E = 0;                        // true_alpha = stored * 2^E
    float pendSc = 1.f;                 // scale folded into the NEXT block's first row
    int   pendE = 0;
    int   curSexp = 0;                  // exponent of pendSc (for next measurement)

    RowP PA[kGroup], PB[kGroup];

    auto gather = [&](int t_base, RowP* P) {   // t_base is a ROW index
#pragma unroll
        for (int j = 0; j < kGroup; j++) {
            const float* row = ring + ((t_base + j) & (kDepth - 1)) * kC;
            float pbv = row[kBlank] + kEps;
            P[j].q13 = add2(pk2(row[lab0], row[lab1]), eps2);
            P[j].q57 = add2(pk2(row[lab2], row[lab3]), eps2);
            P[j].pbb = pk2(pbv, pbv);
            P[j].pb  = pbv;
        }
    };

    auto step = [&](const RowP& r) {
        float a1f, a3f, a5f, a7f;
        unpk2(o01, a1f, a3f);
        unpk2(o23, a5f, a7f);
        float h1 = __shfl_up_sync(0xffffffffu, a7f, 1);   // alpha[8*ln - 1]
        if (ln == 0) h1 = 0.f;
        ull sodd01 = pk2(h1, a1f);        // (a_{-1}, a1)
        ull sodd23 = pk2(a3f, a5f);       // (a3, a5)
        ull in01 = fma2(sk01, sodd01, e01);       // skip-paths for odd states 1,3
        ull in23 = fma2(sk23, sodd23, e23);       // odd states 5,7
        ull ne01 = mul2(add2(e01, sodd01), r.pbb);
        ull ne23 = mul2(add2(e23, sodd23), r.pbb);
        ull no01 = mul2(add2(o01, in01), r.q13);
        ull no23 = mul2(add2(o23, in23), r.q57);
        a8 = (a8 + a7f) * r.pb;           // state 256 (bounded junk on lanes < 31)
        e01 = ne01; e23 = ne23; o01 = no01; o23 = no23;
    };

    // Lazy biased rescale, folded into the block's first-row probabilities:
    // (sc * sum_alpha) * p == sum_alpha * (sc * p), sc a power of 2 -> bit-identical
    // to scaling the alphas. Measurement (pre-fold frame) sets the NEXT block's
    // scale: sexp_next = 227 - eb - sexp_being_applied_now (max -> 2^100).
    auto rescale_fold = [&](RowP* P) {
        ull sc2 = pk2(pendSc, pendSc);
        P[0].pbb = mul2(P[0].pbb, sc2);
        P[0].q13 = mul2(P[0].q13, sc2);
        P[0].q57 = mul2(P[0].q57, sc2);
        P[0].pb *= pendSc;
        E += pendE;
        float x0, x1, x2, x3, y0, y1, y2, y3;
        unpk2(e01, x0, x1); unpk2(e23, x2, x3);
        unpk2(o01, y0, y1); unpk2(o23, y2, y3);
        float m = fmaxf(fmaxf(fmaxf(x0, x1), fmaxf(x2, x3)),
                        fmaxf(fmaxf(y0, y1), fmaxf(y2, fmaxf(y3, a8))));
        uint32_t mm = redux_max_u32(__float_as_uint(m));  // positive fp32: u32 order-preserving
        int eb   = (int)(mm >> 23);
        int sexp = 227 - eb - curSexp;
        if (sexp > 127)  sexp = 127;
        if (sexp < -126) sexp = -126;
        pendSc  = __int_as_float((uint32_t)(sexp + 127) << 23);
        pendE   = -sexp;
        curSexp = sexp;
    };

    // ---- prologue: fill ring (8 groups), gather blocks 0 and 1 ----
    for (int g = 0; g < 8; g++) issue_group(g);
    cp_wait<7>();
    __syncthreads();
    gather(0, PA);                       // rows 0..3  (block 0)
    cp_wait<6>();
    __syncthreads();
    gather(kGroup, PB);                  // rows 4..7  (block 1)

    // ---- block 0: t=0 init + steps 1..3 (data in PA) ----
    if (ln == 0) {
        float q1lo, q1hi;
        unpk2(PA[0].q13, q1lo, q1hi);
        e01 = pk2(PA[0].pb, 0.f);         // alpha0[0] = p_blank
        o01 = pk2(q1lo, 0.f);             // alpha0[1] = p_label0
    }
    step(PA[1]);
    step(PA[2]);
    step(PA[3]);
    issue_group(8);

    // ---- blocks 1..126, ping-pong buffers, gather one block ahead ----
#pragma unroll 1
    for (int g = 1; g < 127; g += 2) {
        // sub-iter g: compute PB (block g), gather block g+1 into PA
        rescale_fold(PB);
        cp_wait<6>();
        __syncthreads();
        gather((g + 1) * kGroup, PA);     // rows 4(g+1) .. 4(g+1)+3
        step(PB[0]); step(PB[1]); step(PB[2]); step(PB[3]);
        issue_group(g + 8);
        // sub-iter g+1: compute PA (block g+1), gather block g+2 into PB
        rescale_fold(PA);
        cp_wait<6>();
        __syncthreads();
        gather((g + 2) * kGroup, PB);     // rows 4(g+2) .. 4(g+2)+3
        step(PA[0]); step(PA[1]); step(PA[2]); step(PA[3]);
        issue_group(g + 9);
    }

    // ---- tail: block 127 (data in PB) ----
    rescale_fold(PB);
    step(PB[0]); step(PB[1]); step(PB[2]); step(PB[3]);

    // loss = -log(alpha[256] + alpha[255]); both live on lane 31.
    if (ln == 31) {
        float a5f, a7f;
        unpk2(o23, a5f, a7f);
        float tot = a8 + a7f;
        out[b] = -(logf(tot) + (float)E * 0.6931471805599453f);
    }
}

extern "C" void kernel_launch(void* const* d_in, const int* in_sizes, int n_in,
                              void* d_out, int out_size) {
    const int* y_true;
    const float* y_pred;
    if (in_sizes[0] == kB * kL) {
        y_true = (const int*)d_in[0];
        y_pred = (const float*)d_in[1];
    } else {
        y_true = (const int*)d_in[1];
        y_pred = (const float*)d_in[0];
    }
    (void)n_in; (void)out_size;
    cudaFuncSetAttribute(ctc_loss_kernel,
                         cudaFuncAttributeMaxDynamicSharedMemorySize, kSmemBytes);
    ctc_loss_kernel<<<kB / 2, 64, kSmemBytes>>>(y_true, y_pred, (float*)d_out);
}

// round 9
// speedup vs baseline: 1.1380x; 1.1380x over previous
#include <cuda_runtime.h>
#include <stdint.h>

// CTC batch loss, prob-domain forward with lazy biased power-of-2 rescaling.
// One warp per batch element (grid=256, block=32). Lane ln owns states
// [8*ln, 8*ln+8) (lane 31 also owns state 256). Alphas as f32x2 pairs.
// KEY (R9): the halo SHFL is software-pipelined ACROSS steps — each step
// computes the h1-independent half (o23/e23) first, issues the shfl of the
// new a7 for the NEXT step, then finishes the h1-dependent half (o01/e01)
// with the PREVIOUS shfl's result. This takes the 26-cycle SHFL latency off
// the per-step critical path (R4/R7/R8 were all bound by it at ~66 cyc/step).
// Rows staged via cp.async in 4-row commit groups (32-row ring, 8 groups in
// flight); gathers double-buffered one block ahead.

namespace {
constexpr int kB = 256, kT = 512, kC = 256, kL = 128;
constexpr int kBlank = kC - 1;          // 255
constexpr float kEps = 1e-7f;
constexpr int kDepth = 32;              // smem ring rows (power of 2)
constexpr int kGroup = 4;               // rows per commit group = steps per block
constexpr int kNG    = kT / kGroup;     // 128 groups

using ull = unsigned long long;

__device__ __forceinline__ void cp_async16(uint32_t saddr, const float* g) {
    asm volatile("cp.async.cg.shared.global [%0], [%1], 16;" :: "r"(saddr), "l"(g));
}
__device__ __forceinline__ void cp_commit() {
    asm volatile("cp.async.commit_group;" ::: "memory");
}
template <int N>
__device__ __forceinline__ void cp_wait() {
    asm volatile("cp.async.wait_group %0;" :: "n"(N) : "memory");
}
__device__ __forceinline__ uint32_t redux_max_u32(uint32_t v) {
    uint32_t r;
    asm volatile("redux.sync.max.u32 %0, %1, 0xffffffff;" : "=r"(r) : "r"(v));
    return r;
}
// f32x2 packed helpers (bit-level pack/unpack are register moves)
__device__ __forceinline__ ull pk2(float lo, float hi) {
    ull r;
    asm("mov.b64 %0, {%1, %2};" : "=l"(r) : "r"(__float_as_uint(lo)), "r"(__float_as_uint(hi)));
    return r;
}
__device__ __forceinline__ void unpk2(ull v, float& lo, float& hi) {
    uint32_t l, h;
    asm("mov.b64 {%0, %1}, %2;" : "=r"(l), "=r"(h) : "l"(v));
    lo = __uint_as_float(l); hi = __uint_as_float(h);
}
__device__ __forceinline__ ull add2(ull a, ull b) {
    ull r; asm("add.rn.f32x2 %0, %1, %2;" : "=l"(r) : "l"(a), "l"(b)); return r;
}
__device__ __forceinline__ ull mul2(ull a, ull b) {
    ull r; asm("mul.rn.f32x2 %0, %1, %2;" : "=l"(r) : "l"(a), "l"(b)); return r;
}
__device__ __forceinline__ ull fma2(ull a, ull b, ull c) {
    ull r; asm("fma.rn.f32x2 %0, %1, %2, %3;" : "=l"(r) : "l"(a), "l"(b), "l"(c)); return r;
}

struct RowP { ull pbb, q13, q57; float pb; };
} // namespace

__global__ void __launch_bounds__(32) ctc_loss_kernel(
    const int* __restrict__ y_true,     // [B, L] int32, values in [0, C-2]
    const float* __restrict__ y_pred,   // [B, T, C] float32 probabilities
    float* __restrict__ out)            // [B] float32 loss
{
    __shared__ __align__(16) float ring[kDepth][kC];   // 32 KB

    const int b  = blockIdx.x;
    const int ln = threadIdx.x;

    // --- labels owned by this lane: indices 4*ln .. 4*ln+3 ---
    const int4 lab4 = reinterpret_cast<const int4*>(y_true + (size_t)b * kL)[ln];
    const int lab0 = lab4.x, lab1 = lab4.y, lab2 = lab4.z, lab3 = lab4.w;
    const int labm1 = __shfl_up_sync(0xffffffffu, lab3, 1);

    // skip for odd state s=2m+1: allowed iff s>=2 and label[m] != label[m-1]
    const float sk0f = (ln > 0 && lab0 != labm1) ? 1.f : 0.f;
    const ull sk01 = pk2(sk0f, (lab1 != lab0) ? 1.f : 0.f);
    const ull sk23 = pk2((lab2 != lab1) ? 1.f : 0.f, (lab3 != lab2) ? 1.f : 0.f);
    const ull eps2 = pk2(kEps, kEps);

    // --- cp.async staging: lane ln copies bytes [32*ln, 32*ln+32) of each 1KB row ---
    const float*   gbase = y_pred + (size_t)b * kT * kC + ln * 8;
    const uint32_t sbase = (uint32_t)__cvta_generic_to_shared(&ring[0][0]) + (uint32_t)ln * 32u;

    auto issue_group = [&](int g) {     // 4 rows per commit group
        if (g < kNG) {
#pragma unroll
            for (int j = 0; j < kGroup; j++) {
                int r = g * kGroup + j;
                uint32_t sa = sbase + (uint32_t)(r & (kDepth - 1)) * (kC * 4);
                const float* ga = gbase + (size_t)r * kC;
                cp_async16(sa, ga);
                cp_async16(sa + 16, ga + 4);
            }
        }
        cp_commit();                    // always commit: wait_group count invariant
    };

    // alphas: e01=(a0,a2) e23=(a4,a6) o01=(a1,a3) o23=(a5,a7); a8 = state 256
    // scalar mirrors of the odd halves avoid unpacks on the critical path
    ull e01 = 0, e23 = 0, o01 = 0, o23 = 0;
    float a1f = 0.f, a3f = 0.f, a5f = 0.f, a7f = 0.f;
    float a8 = 0.f;
    int   E = 0;                        // true_alpha = stored * 2^E
    float pendSc = 1.f;                 // scale folded into the NEXT block's first row
    int   pendE = 0;
    int   curSexp = 0;                  // exponent of pendSc (for next measurement)

    RowP PA[kGroup], PB[kGroup];

    auto gather = [&](int t_base, RowP* P) {   // t_base is a ROW index
#pragma unroll
        for (int j = 0; j < kGroup; j++) {
            const float* row = ring[(t_base + j) & (kDepth - 1)];
            float pbv = row[kBlank] + kEps;
            P[j].q13 = add2(pk2(row[lab0], row[lab1]), eps2);
            P[j].q57 = add2(pk2(row[lab2], row[lab3]), eps2);
            P[j].pbb = pk2(pbv, pbv);
            P[j].pb  = pbv;
        }
    };

    // Pipelined step: h1 = alpha_{t-1}[8*ln-1] (from the PREVIOUS step's shfl).
    // Phase 1 (h1-independent): o23/e23 and the new a7 -> shfl for step t+1.
    // Phase 2 (uses h1): o01/e01 and a8.
    auto step = [&](const RowP& r, float h1) -> float {
        // phase 1
        ull sodd23 = pk2(a3f, a5f);                 // (a3, a5)
        ull in23   = fma2(sk23, sodd23, e23);       // skip-paths states 5,7
        ull ne23   = mul2(add2(e23, sodd23), r.pbb);
        ull no23   = mul2(add2(o23, in23), r.q57);
        float na5, na7;
        unpk2(no23, na5, na7);
        float h1n = __shfl_up_sync(0xffffffffu, na7, 1);  // halo for step t+1
        if (ln == 0) h1n = 0.f;
        // phase 2
        float na8 = (a8 + a7f) * r.pb;              // state 256 (junk on lanes < 31)
        ull sodd01 = pk2(h1, a1f);                  // (a_{-1}, a1)
        ull in01   = fma2(sk01, sodd01, e01);       // skip-paths states 1,3
        ull ne01   = mul2(add2(e01, sodd01), r.pbb);
        ull no01   = mul2(add2(o01, in01), r.q13);
        float na1, na3;
        unpk2(no01, na1, na3);
        e01 = ne01; e23 = ne23; o01 = no01; o23 = no23;
        a1f = na1; a3f = na3; a5f = na5; a7f = na7; a8 = na8;
        return h1n;
    };

    // Lazy biased rescale, folded into the block's first-row probabilities:
    // (sc * sum_alpha) * p == sum_alpha * (sc * p), sc a power of 2 -> bit-identical
    // to scaling the alphas (the pipelined h1 is an addend in those sums, so it is
    // scaled along automatically). Measurement (pre-fold frame) sets the NEXT
    // block's scale: sexp_next = 227 - eb - sexp_being_applied_now (max -> 2^100).
    auto rescale_fold = [&](RowP* P) {
        ull sc2 = pk2(pendSc, pendSc);
        P[0].pbb = mul2(P[0].pbb, sc2);
        P[0].q13 = mul2(P[0].q13, sc2);
        P[0].q57 = mul2(P[0].q57, sc2);
        P[0].pb *= pendSc;
        E += pendE;
        float x0, x1, x2, x3;
        unpk2(e01, x0, x1); unpk2(e23, x2, x3);
        float m = fmaxf(fmaxf(fmaxf(x0, x1), fmaxf(x2, x3)),
                        fmaxf(fmaxf(a1f, a3f), fmaxf(a5f, fmaxf(a7f, a8))));
        uint32_t mm = redux_max_u32(__float_as_uint(m));  // positive fp32: u32 order-preserving
        int eb   = (int)(mm >> 23);
        int sexp = 227 - eb - curSexp;
        if (sexp > 127)  sexp = 127;
        if (sexp < -126) sexp = -126;
        pendSc  = __int_as_float((uint32_t)(sexp + 127) << 23);
        pendE   = -sexp;
        curSexp = sexp;
    };

    // ---- prologue: fill ring (8 groups), gather blocks 0 and 1 ----
    for (int g = 0; g < 8; g++) issue_group(g);
    cp_wait<7>();
    __syncthreads();
    gather(0, PA);                       // rows 0..3  (block 0)
    cp_wait<6>();
    __syncthreads();
    gather(kGroup, PB);                  // rows 4..7  (block 1)

    // ---- block 0: t=0 init + steps 1..3 (data in PA) ----
    if (ln == 0) {
        float q1lo, q1hi;
        unpk2(PA[0].q13, q1lo, q1hi);
        e01 = pk2(PA[0].pb, 0.f);         // alpha0[0] = p_blank
        o01 = pk2(q1lo, 0.f);             // alpha0[1] = p_label0
        a1f = q1lo;
    }
    float h1 = 0.f;                       // alpha0[8*ln-1] = 0 on every lane
    h1 = step(PA[1], h1);
    h1 = step(PA[2], h1);
    h1 = step(PA[3], h1);
    issue_group(8);

    // ---- blocks 1..126, ping-pong buffers, gather one block ahead ----
#pragma unroll 1
    for (int g = 1; g < 127; g += 2) {
        // sub-iter g: compute PB (block g), gather block g+1 into PA
        rescale_fold(PB);
        cp_wait<6>();
        __syncthreads();
        gather((g + 1) * kGroup, PA);     // rows 4(g+1) .. 4(g+1)+3
        h1 = step(PB[0], h1);
        h1 = step(PB[1], h1);
        h1 = step(PB[2], h1);
        h1 = step(PB[3], h1);
        issue_group(g + 8);
        // sub-iter g+1: compute PA (block g+1), gather block g+2 into PB
        rescale_fold(PA);
        cp_wait<6>();
        __syncthreads();
        gather((g + 2) * kGroup, PB);     // rows 4(g+2) .. 4(g+2)+3
        h1 = step(PA[0], h1);
        h1 = step(PA[1], h1);
        h1 = step(PA[2], h1);
        h1 = step(PA[3], h1);
        issue_group(g + 9);
    }

    // ---- tail: block 127 (data in PB) ----
    rescale_fold(PB);
    h1 = step(PB[0], h1);
    h1 = step(PB[1], h1);
    h1 = step(PB[2], h1);
    h1 = step(PB[3], h1);

    // loss = -log(alpha[256] + alpha[255]); both live on lane 31.
    if (ln == 31) {
        float tot = a8 + a7f;
        out[b] = -(logf(tot) + (float)E * 0.6931471805599453f);
    }
}

extern "C" void kernel_launch(void* const* d_in, const int* in_sizes, int n_in,
                              void* d_out, int out_size) {
    const int* y_true;
    const float* y_pred;
    if (in_sizes[0] == kB * kL) {
        y_true = (const int*)d_in[0];
        y_pred = (const float*)d_in[1];
    } else {
        y_true = (const int*)d_in[1];
        y_pred = (const float*)d_in[0];
    }
    (void)n_in; (void)out_size;
    ctc_loss_kernel<<<kB, 32>>>(y_true, y_pred, (float*)d_out);
}

// round 11
// speedup vs baseline: 1.2246x; 1.0760x over previous
#include <cuda_runtime.h>
#include <stdint.h>

// CTC batch loss, prob-domain forward with lazy biased power-of-2 rescaling.
// R10: WARP-SPECIALIZED producer/consumer. One CTA (64 threads) per batch
// element: warp 1 (producer) does ALL cp.async staging into the 32-row smem
// ring; warp 0 (consumer) runs the recurrence (R9 internals: f32x2 packed
// alphas, cross-step pipelined halo SHFL, double-buffered gathers, lazy
// fold-rescale). Rationale: R4/R7/R8/R9 all converged at ~400 cyc/block with
// the SMSP issue port ~94% occupied by ~190 instr/warp/block; moving the ~60
// staging instructions to a sibling warp on another SMSP cuts the critical
// warp's issue work to ~100/block.
// Barrier discipline: producer cp_waits BEFORE each block barrier (data for
// the consumer's next gather resident), and issues the next group AFTER it
// (slot being overwritten was last read before that barrier). 128 barriers
// on both paths.

namespace {
constexpr int kB = 256, kT = 512, kC = 256, kL = 128;
constexpr int kBlank = kC - 1;          // 255
constexpr float kEps = 1e-7f;
constexpr int kDepth = 32;              // smem ring rows (power of 2) = 8 groups
constexpr int kGroup = 4;               // rows per commit group = steps per block
constexpr int kNG    = kT / kGroup;     // 128 groups

using ull = unsigned long long;

__device__ __forceinline__ void cp_async16(uint32_t saddr, const float* g) {
    asm volatile("cp.async.cg.shared.global [%0], [%1], 16;" :: "r"(saddr), "l"(g));
}
__device__ __forceinline__ void cp_commit() {
    asm volatile("cp.async.commit_group;" ::: "memory");
}
template <int N>
__device__ __forceinline__ void cp_wait() {
    asm volatile("cp.async.wait_group %0;" :: "n"(N) : "memory");
}
__device__ __forceinline__ uint32_t redux_max_u32(uint32_t v) {
    uint32_t r;
    asm volatile("redux.sync.max.u32 %0, %1, 0xffffffff;" : "=r"(r) : "r"(v));
    return r;
}
// f32x2 packed helpers (bit-level pack/unpack are register moves)
__device__ __forceinline__ ull pk2(float lo, float hi) {
    ull r;
    asm("mov.b64 %0, {%1, %2};" : "=l"(r) : "r"(__float_as_uint(lo)), "r"(__float_as_uint(hi)));
    return r;
}
__device__ __forceinline__ void unpk2(ull v, float& lo, float& hi) {
    uint32_t l, h;
    asm("mov.b64 {%0, %1}, %2;" : "=r"(l), "=r"(h) : "l"(v));
    lo = __uint_as_float(l); hi = __uint_as_float(h);
}
__device__ __forceinline__ ull add2(ull a, ull b) {
    ull r; asm("add.rn.f32x2 %0, %1, %2;" : "=l"(r) : "l"(a), "l"(b)); return r;
}
__device__ __forceinline__ ull mul2(ull a, ull b) {
    ull r; asm("mul.rn.f32x2 %0, %1, %2;" : "=l"(r) : "l"(a), "l"(b)); return r;
}
__device__ __forceinline__ ull fma2(ull a, ull b, ull c) {
    ull r; asm("fma.rn.f32x2 %0, %1, %2, %3;" : "=l"(r) : "l"(a), "l"(b), "l"(c)); return r;
}

struct RowP { ull pbb, q13, q57; float pb; };
} // namespace

__global__ void __launch_bounds__(64) ctc_loss_kernel(
    const int* __restrict__ y_true,     // [B, L] int32, values in [0, C-2]
    const float* __restrict__ y_pred,   // [B, T, C] float32 probabilities
    float* __restrict__ out)            // [B] float32 loss
{
    __shared__ __align__(16) float ring[kDepth][kC];   // 32 KB

    const int b  = blockIdx.x;
    const int w  = threadIdx.x >> 5;    // 0 = consumer, 1 = producer
    const int ln = threadIdx.x & 31;

    if (w == 1) {
        // ================= PRODUCER WARP =================
        const float*   gbase = y_pred + (size_t)b * kT * kC + ln * 8;
        const uint32_t sbase = (uint32_t)__cvta_generic_to_shared(&ring[0][0])
                             + (uint32_t)ln * 32u;
        auto issue_group = [&](int g) {
            if (g < kNG) {
#pragma unroll
                for (int j = 0; j < kGroup; j++) {
                    int r = g * kGroup + j;
                    uint32_t sa = sbase + (uint32_t)(r & (kDepth - 1)) * (kC * 4);
                    const float* ga = gbase + (size_t)r * kC;
                    cp_async16(sa, ga);
                    cp_async16(sa + 16, ga + 4);
                }
            }
            cp_commit();                // always commit: wait_group count invariant
        };

        for (int g = 0; g < 8; g++) issue_group(g);   // groups 0..7
        cp_wait<6>();                   // groups 0,1 resident (consumer's 2 gathers)
        __syncthreads();                // bar #0
#pragma unroll 1
        for (int g = 1; g < 127; g++) {
            cp_wait<6>();               // groups <= g+1 resident
            __syncthreads();            // bar #g
            issue_group(g + 8);         // overwrites slot g%8: last read before bar #g
        }
        __syncthreads();                // bar #127 (matches consumer tail)
        return;
    }

    // ================= CONSUMER WARP =================
    // --- labels owned by this lane: indices 4*ln .. 4*ln+3 ---
    const int4 lab4 = reinterpret_cast<const int4*>(y_true + (size_t)b * kL)[ln];
    const int lab0 = lab4.x, lab1 = lab4.y, lab2 = lab4.z, lab3 = lab4.w;
    const int labm1 = __shfl_up_sync(0xffffffffu, lab3, 1);

    // skip for odd state s=2m+1: allowed iff s>=2 and label[m] != label[m-1]
    const float sk0f = (ln > 0 && lab0 != labm1) ? 1.f : 0.f;
    const ull sk01 = pk2(sk0f, (lab1 != lab0) ? 1.f : 0.f);
    const ull sk23 = pk2((lab2 != lab1) ? 1.f : 0.f, (lab3 != lab2) ? 1.f : 0.f);
    const ull eps2 = pk2(kEps, kEps);

    // alphas: e01=(a0,a2) e23=(a4,a6) o01=(a1,a3) o23=(a5,a7); a8 = state 256
    ull e01 = 0, e23 = 0, o01 = 0, o23 = 0;
    float a1f = 0.f, a3f = 0.f, a5f = 0.f, a7f = 0.f;
    float a8 = 0.f;
    int   E = 0;                        // true_alpha = stored * 2^E
    float pendSc = 1.f;                 // scale folded into the NEXT block's first row
    int   pendE = 0;
    int   curSexp = 0;

    RowP PA[kGroup], PB[kGroup];

    auto gather = [&](int t_base, RowP* P) {   // t_base is a ROW index
#pragma unroll
        for (int j = 0; j < kGroup; j++) {
            const float* row = ring[(t_base + j) & (kDepth - 1)];
            float pbv = row[kBlank] + kEps;
            P[j].q13 = add2(pk2(row[lab0], row[lab1]), eps2);
            P[j].q57 = add2(pk2(row[lab2], row[lab3]), eps2);
            P[j].pbb = pk2(pbv, pbv);
            P[j].pb  = pbv;
        }
    };

    // Pipelined step: h1 = alpha_{t-1}[8*ln-1] (previous step's shfl).
    auto step = [&](const RowP& r, float h1) -> float {
        // phase 1 (h1-independent)
        ull sodd23 = pk2(a3f, a5f);
        ull in23   = fma2(sk23, sodd23, e23);
        ull ne23   = mul2(add2(e23, sodd23), r.pbb);
        ull no23   = mul2(add2(o23, in23), r.q57);
        float na5, na7;
        unpk2(no23, na5, na7);
        float h1n = __shfl_up_sync(0xffffffffu, na7, 1);  // halo for step t+1
        if (ln == 0) h1n = 0.f;
        // phase 2 (uses h1)
        float na8 = (a8 + a7f) * r.pb;
        ull sodd01 = pk2(h1, a1f);
        ull in01   = fma2(sk01, sodd01, e01);
        ull ne01   = mul2(add2(e01, sodd01), r.pbb);
        ull no01   = mul2(add2(o01, in01), r.q13);
        float na1, na3;
        unpk2(no01, na1, na3);
        e01 = ne01; e23 = ne23; o01 = no01; o23 = no23;
        a1f = na1; a3f = na3; a5f = na5; a7f = na7; a8 = na8;
        return h1n;
    };

    // Lazy biased rescale folded into the block's first-row probabilities
    // (power-of-2 scale -> bit-identical to scaling the alphas directly).
    auto rescale_fold = [&](RowP* P) {
        ull sc2 = pk2(pendSc, pendSc);
        P[0].pbb = mul2(P[0].pbb, sc2);
        P[0].q13 = mul2(P[0].q13, sc2);
        P[0].q57 = mul2(P[0].q57, sc2);
        P[0].pb *= pendSc;
        E += pendE;
        float x0, x1, x2, x3;
        unpk2(e01, x0, x1); unpk2(e23, x2, x3);
        float m = fmaxf(fmaxf(fmaxf(x0, x1), fmaxf(x2, x3)),
                        fmaxf(fmaxf(a1f, a3f), fmaxf(a5f, fmaxf(a7f, a8))));
        uint32_t mm = redux_max_u32(__float_as_uint(m));
        int eb   = (int)(mm >> 23);
        int sexp = 227 - eb - curSexp;      // next max -> 2^100
        if (sexp > 127)  sexp = 127;
        if (sexp < -126) sexp = -126;
        pendSc  = __int_as_float((uint32_t)(sexp + 127) << 23);
        pendE   = -sexp;
        curSexp = sexp;
    };

    __syncthreads();                     // bar #0: groups 0,1 resident
    gather(0, PA);                       // rows 0..3 (block 0)
    gather(kGroup, PB);                  // rows 4..7 (block 1)

    // ---- block 0: t=0 init + steps 1..3 ----
    if (ln == 0) {
        float q1lo, q1hi;
        unpk2(PA[0].q13, q1lo, q1hi);
        e01 = pk2(PA[0].pb, 0.f);        // alpha0[0] = p_blank
        o01 = pk2(q1lo, 0.f);            // alpha0[1] = p_label0
        a1f = q1lo;
    }
    float h1 = 0.f;                      // alpha0[8*ln-1] = 0 on every lane
    h1 = step(PA[1], h1);
    h1 = step(PA[2], h1);
    h1 = step(PA[3], h1);

    // ---- blocks 1..126, ping-pong buffers, gather one block ahead ----
#pragma unroll 1
    for (int g = 1; g < 127; g += 2) {
        rescale_fold(PB);
        __syncthreads();                 // bar #g: group g+1 resident
        gather((g + 1) * kGroup, PA);
        h1 = step(PB[0], h1);
        h1 = step(PB[1], h1);
        h1 = step(PB[2], h1);
        h1 = step(PB[3], h1);
        rescale_fold(PA);
        __syncthreads();                 // bar #g+1: group g+2 resident
        gather((g + 2) * kGroup, PB);
        h1 = step(PA[0], h1);
        h1 = step(PA[1], h1);
        h1 = step(PA[2], h1);
        h1 = step(PA[3], h1);
    }

    // ---- tail: block 127 (data in PB) ----
    rescale_fold(PB);
    __syncthreads();                     // bar #127 (matches producer)
    h1 = step(PB[0], h1);
    h1 = step(PB[1], h1);
    h1 = step(PB[2], h1);
    h1 = step(PB[3], h1);

    // loss = -log(alpha[256] + alpha[255]); both live on lane 31.
    if (ln == 31) {
        float tot = a8 + a7f;
        out[b] = -(logf(tot) + (float)E * 0.6931471805599453f);
    }
}

extern "C" void kernel_launch(void* const* d_in, const int* in_sizes, int n_in,
                              void* d_out, int out_size) {
    const int* y_true;
    const float* y_pred;
    if (in_sizes[0] == kB * kL) {
        y_true = (const int*)d_in[0];
        y_pred = (const float*)d_in[1];
    } else {
        y_true = (const int*)d_in[1];
        y_pred = (const float*)d_in[0];
    }
    (void)n_in; (void)out_size;
    ctc_loss_kernel<<<kB, 64>>>(y_true, y_pred, (float*)d_out);
}

// round 12
// speedup vs baseline: 1.2539x; 1.0240x over previous
#include <cuda_runtime.h>
#include <stdint.h>

// CTC batch loss, prob-domain forward with lazy biased power-of-2 rescaling.
// Warp-specialized: one CTA (64 threads) per batch element; warp 1 (producer)
// stages rows gmem->smem via cp.async; warp 0 (consumer) runs the recurrence
// (f32x2 packed alphas, cross-step pipelined halo SHFL, double-buffered
// gathers, lazy fold-rescale).
// R11 fixes/changes vs R10:
//  * BUGFIX: R10's producer never issued group 8 (loop started at g+8 with
//    g=1), so t=32..35 used stale rows -> rel_err 6.4e-4. New schedule issues
//    group g+S-1 at bar #g with cp_wait<S-3>: every group issued exactly once,
//    groups 0..g+1 guaranteed resident for the consumer's gather at bar #g,
//    and the overwritten slot (g-1)%S has been dead for two barriers.
//  * Ring deepened 32 -> 64 rows (16 groups, 64 KB dynamic smem; 2 CTAs/SM
//    still fit): ~13 blocks of prefetch slack so loaded-DRAM latency jitter
//    no longer stalls the producer's cp_wait (DRAM was 66% and binding).

namespace {
constexpr int kB = 256, kT = 512, kC = 256, kL = 128;
constexpr int kBlank = kC - 1;          // 255
constexpr float kEps = 1e-7f;
constexpr int kDepth = 64;              // smem ring rows (power of 2)
constexpr int kGroup = 4;               // rows per commit group = steps per block
constexpr int kNG    = kT / kGroup;     // 128 groups
constexpr int kS     = kDepth / kGroup; // 16 ring slots (groups)
constexpr int kSmemBytes = kDepth * kC * 4;   // 64 KB dynamic

using ull = unsigned long long;

__device__ __forceinline__ void cp_async16(uint32_t saddr, const float* g) {
    asm volatile("cp.async.cg.shared.global [%0], [%1], 16;" :: "r"(saddr), "l"(g));
}
__device__ __forceinline__ void cp_commit() {
    asm volatile("cp.async.commit_group;" ::: "memory");
}
template <int N>
__device__ __forceinline__ void cp_wait() {
    asm volatile("cp.async.wait_group %0;" :: "n"(N) : "memory");
}
__device__ __forceinline__ uint32_t redux_max_u32(uint32_t v) {
    uint32_t r;
    asm volatile("redux.sync.max.u32 %0, %1, 0xffffffff;" : "=r"(r) : "r"(v));
    return r;
}
// f32x2 packed helpers (bit-level pack/unpack are register moves)
__device__ __forceinline__ ull pk2(float lo, float hi) {
    ull r;
    asm("mov.b64 %0, {%1, %2};" : "=l"(r) : "r"(__float_as_uint(lo)), "r"(__float_as_uint(hi)));
    return r;
}
__device__ __forceinline__ void unpk2(ull v, float& lo, float& hi) {
    uint32_t l, h;
    asm("mov.b64 {%0, %1}, %2;" : "=r"(l), "=r"(h) : "l"(v));
    lo = __uint_as_float(l); hi = __uint_as_float(h);
}
__device__ __forceinline__ ull add2(ull a, ull b) {
    ull r; asm("add.rn.f32x2 %0, %1, %2;" : "=l"(r) : "l"(a), "l"(b)); return r;
}
__device__ __forceinline__ ull mul2(ull a, ull b) {
    ull r; asm("mul.rn.f32x2 %0, %1, %2;" : "=l"(r) : "l"(a), "l"(b)); return r;
}
__device__ __forceinline__ ull fma2(ull a, ull b, ull c) {
    ull r; asm("fma.rn.f32x2 %0, %1, %2, %3;" : "=l"(r) : "l"(a), "l"(b), "l"(c)); return r;
}

struct RowP { ull pbb, q13, q57; float pb; };
} // namespace

__global__ void __launch_bounds__(64) ctc_loss_kernel(
    const int* __restrict__ y_true,     // [B, L] int32, values in [0, C-2]
    const float* __restrict__ y_pred,   // [B, T, C] float32 probabilities
    float* __restrict__ out)            // [B] float32 loss
{
    extern __shared__ __align__(16) float ring[];      // [kDepth][kC], 64 KB

    const int b  = blockIdx.x;
    const int w  = threadIdx.x >> 5;    // 0 = consumer, 1 = producer
    const int ln = threadIdx.x & 31;

    if (w == 1) {
        // ================= PRODUCER WARP =================
        const float*   gbase = y_pred + (size_t)b * kT * kC + ln * 8;
        const uint32_t sbase = (uint32_t)__cvta_generic_to_shared(ring)
                             + (uint32_t)ln * 32u;
        auto issue_group = [&](int g) {
            if (g < kNG) {
#pragma unroll
                for (int j = 0; j < kGroup; j++) {
                    int r = g * kGroup + j;
                    uint32_t sa = sbase + (uint32_t)(r & (kDepth - 1)) * (kC * 4);
                    const float* ga = gbase + (size_t)r * kC;
                    cp_async16(sa, ga);
                    cp_async16(sa + 16, ga + 4);
                }
            }
            cp_commit();                // always commit: wait_group count invariant
        };

        for (int g = 0; g < kS; g++) issue_group(g);   // groups 0..15 (16 commits)
        cp_wait<kS - 2>();              // >=2 complete -> groups 0,1 resident
        __syncthreads();                // bar #0
#pragma unroll 1
        for (int g = 1; g < kNG; g++) {
            // commits before this bar: kS + (g-1) = g+15; <= kS-3 pending
            // -> >= g+2 complete -> groups 0..g+1 resident for consumer.
            cp_wait<kS - 3>();
            __syncthreads();            // bar #g
            // group g+kS-1 -> slot (g-1)%kS: consumer last read it at bar #(g-2).
            issue_group(g + kS - 1);
        }
        return;                         // bars: 1 + 127 = 128 (matches consumer)
    }

    // ================= CONSUMER WARP =================
    // --- labels owned by this lane: indices 4*ln .. 4*ln+3 ---
    const int4 lab4 = reinterpret_cast<const int4*>(y_true + (size_t)b * kL)[ln];
    const int lab0 = lab4.x, lab1 = lab4.y, lab2 = lab4.z, lab3 = lab4.w;
    const int labm1 = __shfl_up_sync(0xffffffffu, lab3, 1);

    // skip for odd state s=2m+1: allowed iff s>=2 and label[m] != label[m-1]
    const float sk0f = (ln > 0 && lab0 != labm1) ? 1.f : 0.f;
    const ull sk01 = pk2(sk0f, (lab1 != lab0) ? 1.f : 0.f);
    const ull sk23 = pk2((lab2 != lab1) ? 1.f : 0.f, (lab3 != lab2) ? 1.f : 0.f);
    const ull eps2 = pk2(kEps, kEps);

    // alphas: e01=(a0,a2) e23=(a4,a6) o01=(a1,a3) o23=(a5,a7); a8 = state 256
    ull e01 = 0, e23 = 0, o01 = 0, o23 = 0;
    float a1f = 0.f, a3f = 0.f, a5f = 0.f, a7f = 0.f;
    float a8 = 0.f;
    int   E = 0;                        // true_alpha = stored * 2^E
    float pendSc = 1.f;                 // scale folded into the NEXT block's first row
    int   pendE = 0;
    int   curSexp = 0;

    RowP PA[kGroup], PB[kGroup];

    auto gather = [&](int t_base, RowP* P) {   // t_base is a ROW index
#pragma unroll
        for (int j = 0; j < kGroup; j++) {
            const float* row = ring + ((t_base + j) & (kDepth - 1)) * kC;
            float pbv = row[kBlank] + kEps;
            P[j].q13 = add2(pk2(row[lab0], row[lab1]), eps2);
            P[j].q57 = add2(pk2(row[lab2], row[lab3]), eps2);
            P[j].pbb = pk2(pbv, pbv);
            P[j].pb  = pbv;
        }
    };

    // Pipelined step: h1 = alpha_{t-1}[8*ln-1] (previous step's shfl).
    auto step = [&](const RowP& r, float h1) -> float {
        // phase 1 (h1-independent)
        ull sodd23 = pk2(a3f, a5f);
        ull in23   = fma2(sk23, sodd23, e23);
        ull ne23   = mul2(add2(e23, sodd23), r.pbb);
        ull no23   = mul2(add2(o23, in23), r.q57);
        float na5, na7;
        unpk2(no23, na5, na7);
        float h1n = __shfl_up_sync(0xffffffffu, na7, 1);  // halo for step t+1
        if (ln == 0) h1n = 0.f;
        // phase 2 (uses h1)
        float na8 = (a8 + a7f) * r.pb;
        ull sodd01 = pk2(h1, a1f);
        ull in01   = fma2(sk01, sodd01, e01);
        ull ne01   = mul2(add2(e01, sodd01), r.pbb);
        ull no01   = mul2(add2(o01, in01), r.q13);
        float na1, na3;
        unpk2(no01, na1, na3);
        e01 = ne01; e23 = ne23; o01 = no01; o23 = no23;
        a1f = na1; a3f = na3; a5f = na5; a7f = na7; a8 = na8;
        return h1n;
    };

    // Lazy biased rescale folded into the block's first-row probabilities
    // (power-of-2 scale -> bit-identical to scaling the alphas directly).
    auto rescale_fold = [&](RowP* P) {
        ull sc2 = pk2(pendSc, pendSc);
        P[0].pbb = mul2(P[0].pbb, sc2);
        P[0].q13 = mul2(P[0].q13, sc2);
        P[0].q57 = mul2(P[0].q57, sc2);
        P[0].pb *= pendSc;
        E += pendE;
        float x0, x1, x2, x3;
        unpk2(e01, x0, x1); unpk2(e23, x2, x3);
        float m = fmaxf(fmaxf(fmaxf(x0, x1), fmaxf(x2, x3)),
                        fmaxf(fmaxf(a1f, a3f), fmaxf(a5f, fmaxf(a7f, a8))));
        uint32_t mm = redux_max_u32(__float_as_uint(m));
        int eb   = (int)(mm >> 23);
        int sexp = 227 - eb - curSexp;      // next max -> 2^100
        if (sexp > 127)  sexp = 127;
        if (sexp < -126) sexp = -126;
        pendSc  = __int_as_float((uint32_t)(sexp + 127) << 23);
        pendE   = -sexp;
        curSexp = sexp;
    };

    __syncthreads();                     // bar #0: groups 0,1 resident
    gather(0, PA);                       // rows 0..3 (block 0)
    gather(kGroup, PB);                  // rows 4..7 (block 1)

    // ---- block 0: t=0 init + steps 1..3 ----
    if (ln == 0) {
        float q1lo, q1hi;
        unpk2(PA[0].q13, q1lo, q1hi);
        e01 = pk2(PA[0].pb, 0.f);        // alpha0[0] = p_blank
        o01 = pk2(q1lo, 0.f);            // alpha0[1] = p_label0
        a1f = q1lo;
    }
    float h1 = 0.f;                      // alpha0[8*ln-1] = 0 on every lane
    h1 = step(PA[1], h1);
    h1 = step(PA[2], h1);
    h1 = step(PA[3], h1);

    // ---- blocks 1..126, ping-pong buffers, gather one block ahead ----
#pragma unroll 1
    for (int g = 1; g < 127; g += 2) {
        rescale_fold(PB);
        __syncthreads();                 // bar #g: group g+1 resident
        gather((g + 1) * kGroup, PA);
        h1 = step(PB[0], h1);
        h1 = step(PB[1], h1);
        h1 = step(PB[2], h1);
        h1 = step(PB[3], h1);
        rescale_fold(PA);
        __syncthreads();                 // bar #g+1: group g+2 resident
        gather((g + 2) * kGroup, PB);
        h1 = step(PA[0], h1);
        h1 = step(PA[1], h1);
        h1 = step(PA[2], h1);
        h1 = step(PA[3], h1);
    }

    // ---- tail: block 127 (data in PB) ----
    rescale_fold(PB);
    __syncthreads();                     // bar #127 (matches producer)
    h1 = step(PB[0], h1);
    h1 = step(PB[1], h1);
    h1 = step(PB[2], h1);
    h1 = step(PB[3], h1);

    // loss = -log(alpha[256] + alpha[255]); both live on lane 31.
    if (ln == 31) {
        float tot = a8 + a7f;
        out[b] = -(logf(tot) + (float)E * 0.6931471805599453f);
    }
}

extern "C" void kernel_launch(void* const* d_in, const int* in_sizes, int n_in,
                              void* d_out, int out_size) {
    const int* y_true;
    const float* y_pred;
    if (in_sizes[0] == kB * kL) {
        y_true = (const int*)d_in[0];
        y_pred = (const float*)d_in[1];
    } else {
        y_true = (const int*)d_in[1];
        y_pred = (const float*)d_in[0];
    }
    (void)n_in; (void)out_size;
    cudaFuncSetAttribute(ctc_loss_kernel,
                         cudaFuncAttributeMaxDynamicSharedMemorySize, kSmemBytes);
    ctc_loss_kernel<<<kB, 64, kSmemBytes>>>(y_true, y_pred, (float*)d_out);
}